// round 12
// baseline (speedup 1.0000x reference)
#include <cuda_runtime.h>
#include <math.h>
#include <stdint.h>

#define BN   8
#define TN   16
#define CINC 3
#define HD   64
#define HH   64
#define WWN  64
#define HW   4096

#define TW    32
#define TH    8
#define COT   16                       // co per block = 8 copairs
#define CHUNK 4
#define NCH   (HD / CHUNK)             // 16 chunks
#define RSU   36                       // row stride in u64 (34 used + pad), 16B mult
#define PATCHU (10 * RSU)              // 360 u64 per channel patch
#define PBUFU  (8 * PATCHU)            // 2880 u64 per chunk buffer
#define SLICE  720                     // floats per quarter-slice (PBUF floats / 4)
#define WCNT   1536                    // u64 weights per stage
#define SMEMB  ((2 * PBUFU + 2 * WCNT) * 8)   // 70,656 bytes dynamic smem

typedef unsigned long long u64;

__device__ float g_c[2][BN * HD * HW];
// packed weights: [co-block][stage 0..16][WCNT]; stage 0 = x/time, s>=1 = chunk s-1
__device__ u64 g_w[4][NCH + 1][WCNT];

__device__ __forceinline__ void ffma2(u64 &d, u64 a, u64 b) {
    asm("fma.rn.f32x2 %0, %1, %2, %0;" : "+l"(d) : "l"(a), "l"(b));
}
__device__ __forceinline__ u64 pack2(float x, float y) {
    u64 r;
    asm("mov.b64 %0, {%1, %2};" : "=l"(r) : "f"(x), "f"(y));
    return r;
}
__device__ __forceinline__ float2 unpack2(u64 v) {
    float2 r;
    asm("mov.b64 {%0, %1}, %2;" : "=f"(r.x), "=f"(r.y) : "l"(v));
    return r;
}
__device__ __forceinline__ float sigmoidf_(float x) {
    return 1.0f / (1.0f + __expf(-x));
}
__device__ __forceinline__ void cp_async4(uint32_t dst, const void *src, uint32_t sz) {
    asm volatile("cp.async.ca.shared.global [%0], [%1], 4, %2;"
                 :: "r"(dst), "l"(src), "r"(sz));
}
__device__ __forceinline__ void cp_async16(uint32_t dst, const void *src) {
    asm volatile("cp.async.ca.shared.global [%0], [%1], 16;"
                 :: "r"(dst), "l"(src));
}
__device__ __forceinline__ void cp_commit() {
    asm volatile("cp.async.commit_group;" ::: "memory");
}
__device__ __forceinline__ void cp_wait0() {
    asm volatile("cp.async.wait_group 0;" ::: "memory");
}

// weight index: base of the 4-u64 group for (tns, cc, cp, ky); kx in [0,3)
__device__ __forceinline__ int widx(int tns, int cc, int cp, int ky) {
    return (((tns * 4 + cc) * 8 + cp) * 3 + ky) * 4;
}

// 10 (v,v)-duplicated pv values of one patch row: 5 aligned 16B loads, no MOVs
__device__ __forceinline__ void loadrow10(const u64 *__restrict__ row, u64 pv[10]) {
#pragma unroll
    for (int q = 0; q < 5; q++) {
        ulonglong2 p = *(const ulonglong2 *)(row + q * 2);
        pv[q * 2] = p.x;
        pv[q * 2 + 1] = p.y;
    }
}

// ===================== weight pre-packing kernel =============================
__global__ void pack_weights(const float *__restrict__ Wi, const float *__restrict__ Wct,
                             const float *__restrict__ Wo, const float *__restrict__ Wcs) {
    int idx = blockIdx.x * 256 + threadIdx.x;
    const int TOT = 4 * (NCH + 1) * WCNT;
    if (idx >= TOT) return;
    int e = idx % WCNT;
    int s = (idx / WCNT) % (NCH + 1);
    int cb = idx / (WCNT * (NCH + 1));
    int kx = e & 3;
    int q = e >> 2;
    int ky = q % 3; q /= 3;
    int cp = q % 8; q /= 8;
    int cc = q % 4;
    int tns = q / 4;
    int co0 = cb * COT + cp * 2;
    float w0 = 0.0f, w1 = 0.0f;
    if (kx < 3) {
        int kk = ky * 3 + kx;
        if (s == 0) {
            if (tns < 3 && cc < 3) {           // x channels
                int ci = cc;
                if (tns == 0) {
                    w0 = Wi[((size_t)co0 * 67 + ci) * 9 + kk];
                    w1 = Wi[((size_t)(co0 + 1) * 67 + ci) * 9 + kk];
                } else if (tns == 1) {
                    w0 = Wct[((size_t)co0 * 67 + ci) * 9 + kk];
                    w1 = Wct[((size_t)(co0 + 1) * 67 + ci) * 9 + kk];
                } else {
                    w0 = Wo[((size_t)co0 * 68 + ci) * 9 + kk];
                    w1 = Wo[((size_t)(co0 + 1) * 68 + ci) * 9 + kk];
                }
            } else if (tns == 2 && cc == 3) {  // time channel -> o-gate weights
                w0 = Wo[((size_t)co0 * 68 + 67) * 9 + kk];
                w1 = Wo[((size_t)(co0 + 1) * 68 + 67) * 9 + kk];
            }
        } else {
            int j = (s - 1) * CHUNK + cc;
            if (tns == 0) {
                w0 = Wi[((size_t)co0 * 67 + 3 + j) * 9 + kk];
                w1 = Wi[((size_t)(co0 + 1) * 67 + 3 + j) * 9 + kk];
            } else if (tns == 1) {
                w0 = Wct[((size_t)co0 * 67 + 3 + j) * 9 + kk];
                w1 = Wct[((size_t)(co0 + 1) * 67 + 3 + j) * 9 + kk];
            } else if (tns == 2) {
                w0 = Wo[((size_t)co0 * 68 + 3 + j) * 9 + kk];
                w1 = Wo[((size_t)(co0 + 1) * 68 + 3 + j) * 9 + kk];
            } else {
                w0 = Wcs[((size_t)co0 * 64 + j) * 9 + kk];
                w1 = Wcs[((size_t)(co0 + 1) * 64 + j) * 9 + kk];
            }
        }
    }
    g_w[cb][s][e] = pack2(w0, w1);
}

// ===================== main step kernel ======================================
// Tile 32x8, 8 px/thread. Patches stored DUPLICATED (v,v) as u64, staged by
// paired cp.async (dst, dst+4 from same src) -> zero dup MOVs in hot loop.
// Warp specialization: warps 0-5 own i/ct/o (h patches), warps 6-7 own cs
// (c patches). Two-phase epilogue exchange through smem overlay.
template <bool FIRST, bool LAST>
__global__ void __launch_bounds__(256, 2)
lstm_step(const float *__restrict__ input, const float *__restrict__ timet,
          const float *__restrict__ bi, const float *__restrict__ bct,
          const float *__restrict__ bo, const float *__restrict__ bcs,
          float *__restrict__ out, float *__restrict__ hlast,
          float *__restrict__ clast, int t) {
    extern __shared__ __align__(16) u64 dyn[];
    u64 *spu = dyn;                        // 2 * PBUFU duplicated patches
    u64 *wsmf = dyn + 2 * PBUFU;           // 2 * WCNT weights
    u64 *ex = dyn;                         // epilogue overlay (4096 u64)

    const int tid = threadIdx.x;
    const int w = tid >> 5;
    const int lane = tid & 31;
    const int tx = lane & 3;     // 8-px group
    const int ty = lane >> 2;    // row

    int tnsw, cp0, pslot;
    if (w < 6) { tnsw = w >> 1; cp0 = (w & 1) * 4; pslot = 0; }
    else       { tnsw = 3;      cp0 = (w - 6) * 4; pslot = 4; }

    const int tile_x = (blockIdx.x & 1) * TW;
    const int tile_y = (blockIdx.x >> 1) * TH;
    const int cb = blockIdx.y;
    const int co_base = cb * COT;
    const int b = blockIdx.z;

    const float *xb  = input + ((size_t)(b * TN + t) * CINC) * HW;
    const float *tmb = timet + ((size_t)(b * TN + t)) * HW;
    float *outb = out + ((size_t)(b * TN + t) * HD) * HW;
    const float *hprev = FIRST ? nullptr
                               : out + ((size_t)(b * TN + t - 1) * HD) * HW;
    const float *cprev = &g_c[t & 1][(size_t)b * HD * HW];
    float *cnext = &g_c[(t & 1) ^ 1][(size_t)b * HD * HW];

    const uint32_t sp_sm = (uint32_t)__cvta_generic_to_shared(spu);
    const uint32_t w_sm = (uint32_t)__cvta_generic_to_shared(wsmf);

    // acc[unit 0..3][px 0..7]; unit u = (tnsw, cp0+u), fp32x2 over copair
    u64 acc[4][8];
    {
        const float *bp = (tnsw == 0) ? bi : (tnsw == 1) ? bct
                        : (tnsw == 2) ? bo : bcs;
#pragma unroll
        for (int u = 0; u < 4; u++) {
            int co0 = co_base + (cp0 + u) * 2;
            u64 v = pack2(bp[co0], bp[co0 + 1]);
#pragma unroll
            for (int px = 0; px < 8; px++) acc[u][px] = v;
        }
    }

    auto load_weights_async = [&](int wbuf, int s) {
        const u64 *src = &g_w[cb][s][0];
        const uint32_t dstb = w_sm + (uint32_t)wbuf * WCNT * 8;
#pragma unroll
        for (int k = 0; k < 3; k++) {
            int e = tid + k * 256;              // 768 x 16B
            if (e < WCNT / 2)
                cp_async16(dstb + (uint32_t)e * 16, src + (size_t)e * 2);
        }
    };

    // quarter-slice s of chunk j0 -> duplicated (v,v) u64 pairs via 2x cp.async
    auto load_patch_slice = [&](int buf, int j0, int s) {
        const uint32_t dstb = sp_sm + (uint32_t)buf * PBUFU * 8;
#pragma unroll
        for (int k = 0; k < 3; k++) {
            int e = s * SLICE + tid + k * 256;
            if (e < (s + 1) * SLICE) {
                int slot = e / PATCHU, pos = e % PATCHU;
                int r = pos / RSU, c = pos % RSU;
                int gy = tile_y - 1 + r, gx = tile_x - 1 + c;
                bool inb = (c < TW + 2) && ((unsigned)gy < HH) && ((unsigned)gx < WWN);
                const float *pl = (slot < 4)
                                      ? hprev + (size_t)(j0 + slot) * HW
                                      : cprev + (size_t)(j0 + slot - 4) * HW;
                const float *src = pl + (inb ? (gy * WWN + gx) : 0);
                uint32_t d0 = dstb + (uint32_t)e * 8;
                cp_async4(d0, src, inb ? 4u : 0u);
                cp_async4(d0 + 4, src, inb ? 4u : 0u);
            }
        }
    };

    // convolve channels [cc0, ccN) of patch block pbase into acc
    auto conv_spec = [&](const u64 *pbase, const u64 *wb, int cc0, int ccN) {
        for (int cc = cc0; cc < ccN; cc++) {
            const u64 *pch = pbase + cc * PATCHU;
#pragma unroll
            for (int ky = 0; ky < 3; ky++) {
                u64 pv[10];
                loadrow10(pch + (ty + ky) * RSU + tx * 8, pv);
#pragma unroll
                for (int u = 0; u < 4; u++) {
                    int base = widx(tnsw, cc, cp0 + u, ky);
                    ulonglong2 w01 = *(const ulonglong2 *)&wb[base];
                    u64 w2 = wb[base + 2];
#pragma unroll
                    for (int px = 0; px < 8; px++) {
                        ffma2(acc[u][px], pv[px], w01.x);
                        ffma2(acc[u][px], pv[px + 1], w01.y);
                        ffma2(acc[u][px], pv[px + 2], w2);
                    }
                }
            }
        }
    };

    // ===== stage 0: x(3)+time patches into buf1, weights s=0 into wbuf1 =====
    {
        const uint32_t dstb = sp_sm + (uint32_t)PBUFU * 8;  // buf 1
#pragma unroll
        for (int k = 0; k < 6; k++) {
            int e = tid + k * 256;
            if (e < 4 * PATCHU) {
                int slot = e / PATCHU, pos = e % PATCHU;
                int r = pos / RSU, c = pos % RSU;
                int gy = tile_y - 1 + r, gx = tile_x - 1 + c;
                bool inb = (c < TW + 2) && ((unsigned)gy < HH) && ((unsigned)gx < WWN);
                const float *pl = (slot < 3) ? xb + (size_t)slot * HW : tmb;
                const float *src = pl + (inb ? (gy * WWN + gx) : 0);
                uint32_t d0 = dstb + (uint32_t)e * 8;
                cp_async4(d0, src, inb ? 4u : 0u);
                cp_async4(d0 + 4, src, inb ? 4u : 0u);
            }
        }
        load_weights_async(1, 0);
        cp_commit();
        cp_wait0();
        __syncthreads();
    }

    // prefetch chunk 0 while computing stage 0
    if (!FIRST) {
        load_weights_async(0, 1);
#pragma unroll
        for (int s = 0; s < 4; s++) load_patch_slice(0, 0, s);
        cp_commit();
    }

    // stage-0 compute: h-warps only. o-warps also take cc=3 (time channel).
    if (w < 6)
        conv_spec(spu + PBUFU, wsmf + WCNT, 0, (tnsw == 2) ? 4 : 3);

    if (!FIRST) cp_wait0();
    __syncthreads();

    // ===== pipelined chunk loop =====
    if (!FIRST) {
#pragma unroll 1
        for (int jc = 0; jc < NCH; jc++) {
            const int buf = jc & 1;
            const bool pre = (jc < NCH - 1);
            const u64 *pb = spu + buf * PBUFU + pslot * PATCHU;
            const u64 *wb = wsmf + buf * WCNT;
            if (pre) {
                load_weights_async(buf ^ 1, jc + 2);
                load_patch_slice(buf ^ 1, (jc + 1) * CHUNK, 0);
                load_patch_slice(buf ^ 1, (jc + 1) * CHUNK, 1);
                cp_commit();
            }
            conv_spec(pb, wb, 0, 2);
            if (pre) {
                load_patch_slice(buf ^ 1, (jc + 1) * CHUNK, 2);
                load_patch_slice(buf ^ 1, (jc + 1) * CHUNK, 3);
                cp_commit();
            }
            conv_spec(pb, wb, 2, 4);
            if (pre) cp_wait0();
            __syncthreads();
        }
    }

    // ===== epilogue: two-phase acc exchange, then pointwise update =====
    const int pos0w = ty * TW + tx * 8;        // writer base position
    const int cp = w;                          // reader copair
    const int pos0r = (lane >> 2) * TW + (lane & 3) * 8;

    u64 fa[2][8], fb[2][8];
    // phase A write: warps 0..3 (tnsw 0,1)
    if (tnsw < 2) {
#pragma unroll
        for (int u = 0; u < 4; u++) {
            int base = (tnsw * 8 + cp0 + u) * 256 + pos0w;
#pragma unroll
            for (int q = 0; q < 4; q++)
                *(ulonglong2 *)&ex[base + q * 2] =
                    make_ulonglong2(acc[u][q * 2], acc[u][q * 2 + 1]);
        }
    }
    __syncthreads();
#pragma unroll
    for (int tn = 0; tn < 2; tn++) {
        int base = (tn * 8 + cp) * 256 + pos0r;
#pragma unroll
        for (int q = 0; q < 4; q++) {
            ulonglong2 p = *(const ulonglong2 *)&ex[base + q * 2];
            fa[tn][q * 2] = p.x; fa[tn][q * 2 + 1] = p.y;
        }
    }
    __syncthreads();
    // phase B write: warps 4..7 (tnsw 2,3)
    if (tnsw >= 2) {
#pragma unroll
        for (int u = 0; u < 4; u++) {
            int base = ((tnsw - 2) * 8 + cp0 + u) * 256 + pos0w;
#pragma unroll
            for (int q = 0; q < 4; q++)
                *(ulonglong2 *)&ex[base + q * 2] =
                    make_ulonglong2(acc[u][q * 2], acc[u][q * 2 + 1]);
        }
    }
    __syncthreads();
#pragma unroll
    for (int tn = 0; tn < 2; tn++) {
        int base = (tn * 8 + cp) * 256 + pos0r;
#pragma unroll
        for (int q = 0; q < 4; q++) {
            ulonglong2 p = *(const ulonglong2 *)&ex[base + q * 2];
            fb[tn][q * 2] = p.x; fb[tn][q * 2 + 1] = p.y;
        }
    }

    const int yy = tile_y + (lane >> 2);
    const int xx0 = tile_x + (lane & 3) * 8;
    float tmv[8];
    {
        float4 t0 = *(const float4 *)(tmb + yy * WWN + xx0);
        float4 t1 = *(const float4 *)(tmb + yy * WWN + xx0 + 4);
        tmv[0] = tanhf(t0.x); tmv[1] = tanhf(t0.y); tmv[2] = tanhf(t0.z);
        tmv[3] = tanhf(t0.w); tmv[4] = tanhf(t1.x); tmv[5] = tanhf(t1.y);
        tmv[6] = tanhf(t1.z); tmv[7] = tanhf(t1.w);
    }

#pragma unroll
    for (int half = 0; half < 2; half++) {
        const int co = co_base + cp * 2 + half;
        const size_t pbase = (size_t)co * HW + (size_t)yy * WWN + xx0;
        float cpv[8];
        if (FIRST) {
#pragma unroll
            for (int px = 0; px < 8; px++) cpv[px] = 0.0f;
        } else {
            float4 c0 = *(const float4 *)(cprev + pbase);
            float4 c1 = *(const float4 *)(cprev + pbase + 4);
            cpv[0] = c0.x; cpv[1] = c0.y; cpv[2] = c0.z; cpv[3] = c0.w;
            cpv[4] = c1.x; cpv[5] = c1.y; cpv[6] = c1.z; cpv[7] = c1.w;
        }
        float hn[8], cn[8];
#pragma unroll
        for (int px = 0; px < 8; px++) {
            float2 vi = unpack2(fa[0][px]);
            float2 vq = unpack2(fa[1][px]);
            float2 vo = unpack2(fb[0][px]);
            float2 vs = unpack2(fb[1][px]);
            float gi = half ? vi.y : vi.x;
            float gq = half ? vq.y : vq.x;
            float go = half ? vo.y : vo.x;
            float gs = half ? vs.y : vs.x;
            float ig = sigmoidf_(gi);             // f gate == i gate (ref bug)
            float cstar = cpv[px] - gs * (1.0f + tmv[px]);
            float ctl = tanhf(gq);
            cn[px] = ig * (cstar + ctl);
            float og = sigmoidf_(go);
            hn[px] = og * tanhf(cn[px]);
        }
        *(float4 *)(outb + pbase) = make_float4(hn[0], hn[1], hn[2], hn[3]);
        *(float4 *)(outb + pbase + 4) = make_float4(hn[4], hn[5], hn[6], hn[7]);
        *(float4 *)(cnext + pbase) = make_float4(cn[0], cn[1], cn[2], cn[3]);
        *(float4 *)(cnext + pbase + 4) = make_float4(cn[4], cn[5], cn[6], cn[7]);
        if (LAST && hlast != nullptr) {
            size_t lb = ((size_t)b * HD + co) * HW + (size_t)yy * WWN + xx0;
            *(float4 *)(hlast + lb) = make_float4(hn[0], hn[1], hn[2], hn[3]);
            *(float4 *)(hlast + lb + 4) = make_float4(hn[4], hn[5], hn[6], hn[7]);
            *(float4 *)(clast + lb) = make_float4(cn[0], cn[1], cn[2], cn[3]);
            *(float4 *)(clast + lb + 4) = make_float4(cn[4], cn[5], cn[6], cn[7]);
        }
    }
}

extern "C" void kernel_launch(void *const *d_in, const int *in_sizes, int n_in,
                              void *d_out, int out_size) {
    (void)in_sizes; (void)n_in;
    const float *input = (const float *)d_in[0];
    const float *timet = (const float *)d_in[1];
    const float *Wi  = (const float *)d_in[2];
    const float *bi  = (const float *)d_in[3];
    const float *Wct = (const float *)d_in[4];
    const float *bct = (const float *)d_in[5];
    const float *Wo  = (const float *)d_in[6];
    const float *bo  = (const float *)d_in[7];
    const float *Wcs = (const float *)d_in[8];
    const float *bcs = (const float *)d_in[9];
    float *out = (float *)d_out;

    const size_t layer_elems = (size_t)BN * TN * HD * HW;
    const size_t hc = (size_t)BN * HD * HW;
    const bool tail = (size_t)out_size >= layer_elems + 2 * hc;
    float *hlast = tail ? out + layer_elems : nullptr;
    float *clast = tail ? out + layer_elems + hc : nullptr;

    // opt-in dynamic smem > 48KB (idempotent; not a stream op)
    cudaFuncSetAttribute(lstm_step<true, false>,
                         cudaFuncAttributeMaxDynamicSharedMemorySize, SMEMB);
    cudaFuncSetAttribute(lstm_step<false, false>,
                         cudaFuncAttributeMaxDynamicSharedMemorySize, SMEMB);
    cudaFuncSetAttribute(lstm_step<false, true>,
                         cudaFuncAttributeMaxDynamicSharedMemorySize, SMEMB);

    {   // pack weights once per launch (stream-ordered before the steps)
        const int TOT = 4 * (NCH + 1) * WCNT;
        pack_weights<<<(TOT + 255) / 256, 256>>>(Wi, Wct, Wo, Wcs);
    }

    dim3 grid(16, HD / COT, BN);   // 2 x-tiles * 8 y-tiles, 4 co-blocks, 8 batch
    for (int t = 0; t < TN; t++) {
        if (t == 0)
            lstm_step<true, false><<<grid, 256, SMEMB>>>(input, timet, bi, bct,
                                                         bo, bcs, out, nullptr,
                                                         nullptr, t);
        else if (t == TN - 1)
            lstm_step<false, true><<<grid, 256, SMEMB>>>(input, timet, bi, bct,
                                                         bo, bcs, out, hlast,
                                                         clast, t);
        else
            lstm_step<false, false><<<grid, 256, SMEMB>>>(input, timet, bi, bct,
                                                          bo, bcs, out, nullptr,
                                                          nullptr, t);
    }
}